// round 2
// baseline (speedup 1.0000x reference)
#include <cuda_runtime.h>

// ---------------- f32x2 helpers (Blackwell packed fp32: doubles FFMA rate) ----
static __device__ __forceinline__ unsigned long long pk2(float a, float b){
    unsigned long long r; asm("mov.b64 %0,{%1,%2};" : "=l"(r) : "f"(a), "f"(b)); return r;
}
static __device__ __forceinline__ float2 up2(unsigned long long v){
    float2 r; asm("mov.b64 {%0,%1},%2;" : "=f"(r.x), "=f"(r.y) : "l"(v)); return r;
}
static __device__ __forceinline__ void fma2(unsigned long long &d, unsigned long long a, unsigned long long b){
    asm("fma.rn.f32x2 %0,%1,%2,%0;" : "+l"(d) : "l"(a), "l"(b));
}
static __device__ __forceinline__ unsigned long long ld2(const float* p){
    return *reinterpret_cast<const unsigned long long*>(p);
}

// ---------------- scratch (device globals: no allocations allowed) -----------
__device__ float g_c1[32u*128*128*32];   // conv1 out  [B,128,128,32]  67 MB
__device__ float g_c2[32u*64*64*64];     // conv2 out  [B,64,64,64]    33.5 MB
__device__ float g_part[256*32*128];     // FC1 split-K partials       4 MB
__device__ float g_x[32*128];            // FC1 out (post relu)
__device__ float g_theta[32*6];          // FC2 out

// ================= conv1: 3x3 s2 SAME, 3->32, relu ===========================
// one thread per output pixel, 32 channels as 16 f32x2 accumulators.
__global__ void __launch_bounds__(256) k_conv1(const float* __restrict__ in,
                                               const float* __restrict__ k1,
                                               const float* __restrict__ b1){
    __shared__ float sw[864];   // [ky][kx][ci][32]
    __shared__ float sb[32];
    for(int i=threadIdx.x;i<864;i+=256) sw[i]=k1[i];
    if(threadIdx.x<32) sb[threadIdx.x]=b1[threadIdx.x];
    __syncthreads();

    int idx = blockIdx.x*256 + threadIdx.x;          // 32*128*128 = 524288
    int ox = idx & 127, oy = (idx>>7)&127, b = idx>>14;

    unsigned long long acc[16];
    #pragma unroll
    for(int j=0;j<16;j++) acc[j]=pk2(sb[2*j],sb[2*j+1]);

    const float* ib = in + (size_t)b*256*256*3;
    #pragma unroll
    for(int ky=0;ky<3;ky++){
        int iy = 2*oy+ky;                            // SAME pad_lo = 0
        if(iy>=256) break;
        #pragma unroll
        for(int kx=0;kx<3;kx++){
            int ix = 2*ox+kx;
            if(ix>=256) continue;
            const float* p = ib + (iy*256+ix)*3;
            #pragma unroll
            for(int ci=0;ci<3;ci++){
                float v = p[ci];
                unsigned long long vv = pk2(v,v);
                const float* w = sw + ((ky*3+kx)*3+ci)*32;
                #pragma unroll
                for(int j=0;j<16;j++) fma2(acc[j], vv, ld2(w+2*j));
            }
        }
    }
    float2* o = reinterpret_cast<float2*>(g_c1 + (size_t)idx*32);
    #pragma unroll
    for(int j=0;j<16;j++){
        float2 v = up2(acc[j]);
        v.x = v.x>0.f? v.x:0.f; v.y = v.y>0.f? v.y:0.f;
        o[j] = v;
    }
}

// ================= conv2: 3x3 s2 SAME, 32->64, relu ==========================
// block: 16x16 output tile of one image. 128 threads; each thread = 4 pixels
// (same column, 4 rows) x 32 output channels (one half). Two ci-group passes
// (16 ci each) so smem = 104 KB -> 2 blocks/SM.
// patch smem layout [ci][ry][rx] (1089 = 33*33, odd strides -> conflict-free).
__global__ void __launch_bounds__(128) k_conv2(const float* __restrict__ k2,
                                               const float* __restrict__ b2){
    extern __shared__ float sm[];
    float* sp  = sm;            // 16*1089 = 17424 floats
    float* swt = sm + 17424;    // 9*16*64 = 9216 floats   (byte off 69696 % 8 == 0)

    int t = threadIdx.x;
    int ox0 = blockIdx.x*16, oy0 = blockIdx.y*16, b = blockIdx.z;
    int h   = t>>6;             // channel half
    int pt  = t&63;
    int oxl = pt&15, oyq = pt>>4;   // rows oyq*4 .. oyq*4+3

    unsigned long long acc[4][16];
    #pragma unroll
    for(int j=0;j<16;j++){
        unsigned long long vv = pk2(b2[h*32+2*j], b2[h*32+2*j+1]);
        #pragma unroll
        for(int k=0;k<4;k++) acc[k][j]=vv;
    }

    const float* inb = g_c1 + (size_t)b*128*128*32;

    for(int g=0; g<2; g++){
        __syncthreads();
        // weights for this ci-group: [tap][ci_l][64]
        for(int i=t;i<9216;i+=128){
            int c = i&63, rest = i>>6;          // rest = tap*16+ci_l
            swt[i] = k2[((rest>>4)*32 + g*16 + (rest&15))*64 + c];
        }
        // input patch 33x33x16 (zero-fill OOB)
        for(int i=t;i<16*1089;i+=128){
            int ci = i&15, rc = i>>4;
            int ry = rc/33, rx = rc - ry*33;
            int iy = oy0*2+ry, ix = ox0*2+rx;
            float v = 0.f;
            if(iy<128 && ix<128) v = inb[(((iy<<7)+ix)<<5) + g*16 + ci];
            sp[ci*1089 + rc] = v;
        }
        __syncthreads();

        #pragma unroll
        for(int ky=0;ky<3;ky++){
            #pragma unroll
            for(int kx=0;kx<3;kx++){
                const float* wrow = swt + (ky*3+kx)*16*64 + h*32;
                int pbase = ky*33 + kx + oxl*2 + oyq*4*66;
                for(int ci=0;ci<16;ci++){
                    const float* pc = sp + ci*1089 + pbase;
                    float v0 = pc[0*66], v1 = pc[1*66], v2 = pc[2*66], v3 = pc[3*66];
                    unsigned long long a0=pk2(v0,v0), a1=pk2(v1,v1),
                                       a2=pk2(v2,v2), a3=pk2(v3,v3);
                    const float* w = wrow + ci*64;
                    #pragma unroll
                    for(int j=0;j<16;j++){
                        unsigned long long wv = ld2(w + 2*j);
                        fma2(acc[0][j], a0, wv);
                        fma2(acc[1][j], a1, wv);
                        fma2(acc[2][j], a2, wv);
                        fma2(acc[3][j], a3, wv);
                    }
                }
            }
        }
    }
    #pragma unroll
    for(int k=0;k<4;k++){
        int oy = oy0 + oyq*4 + k, ox = ox0 + oxl;
        float2* o = reinterpret_cast<float2*>(
            g_c2 + (((size_t)b*64 + oy)*64 + ox)*64 + h*32);
        #pragma unroll
        for(int j=0;j<16;j++){
            float2 v = up2(acc[k][j]);
            v.x = v.x>0.f? v.x:0.f; v.y = v.y>0.f? v.y:0.f;
            o[j] = v;
        }
    }
}

// ================= FC1: [32,262144] @ [262144,128], split-K ==================
// 256 blocks = K-chunks of 1024. Block 128 thr = 32 n-quads x 4 m-groups.
// A chunk staged in smem [kk][m] (stride 34, m-pairs 8B aligned); B streamed
// as float4. f32x2 over m-pairs, b broadcast-packed.
__global__ void __launch_bounds__(128) k_fc1(const float* __restrict__ w1){
    extern __shared__ float sa[];        // 512*34 floats
    int t = threadIdx.x;
    int nq = t & 31, mt = t >> 5;        // n = nq*4+j, m-pairs = mt*4+i
    int k0 = blockIdx.x * 1024;

    unsigned long long acc[4][4];
    #pragma unroll
    for(int i=0;i<4;i++)
        #pragma unroll
        for(int j=0;j<4;j++) acc[i][j]=0ull;

    for(int tile=0;tile<2;tile++){
        int kb = k0 + tile*512;
        __syncthreads();
        for(int i=t;i<16384;i+=128){
            int m = i>>9, kk = i&511;
            sa[kk*34+m] = g_c2[(size_t)m*262144 + kb + kk];
        }
        __syncthreads();
        #pragma unroll 8
        for(int kk=0;kk<512;kk++){
            float4 bv = *reinterpret_cast<const float4*>(
                w1 + (size_t)(kb+kk)*128 + nq*4);
            unsigned long long b0=pk2(bv.x,bv.x), b1=pk2(bv.y,bv.y),
                               b2=pk2(bv.z,bv.z), b3=pk2(bv.w,bv.w);
            const float* ap = sa + kk*34 + mt*8;
            #pragma unroll
            for(int i=0;i<4;i++){
                unsigned long long a2 = ld2(ap + 2*i);
                fma2(acc[i][0], a2, b0);
                fma2(acc[i][1], a2, b1);
                fma2(acc[i][2], a2, b2);
                fma2(acc[i][3], a2, b3);
            }
        }
    }
    float* pb = g_part + (size_t)blockIdx.x*4096;
    #pragma unroll
    for(int i=0;i<4;i++){
        int m0 = mt*8 + 2*i;
        #pragma unroll
        for(int j=0;j<4;j++){
            float2 v = up2(acc[i][j]);
            pb[m0*128     + nq*4 + j] = v.x;
            pb[(m0+1)*128 + nq*4 + j] = v.y;
        }
    }
}

// partial reduce + bias + relu
__global__ void k_fc1red(const float* __restrict__ d1){
    int t = blockIdx.x*256 + threadIdx.x;    // 4096
    float s = d1[t & 127];
    for(int c=0;c<256;c++) s += g_part[c*4096 + t];
    g_x[t] = s>0.f? s:0.f;
}

// ================= FC2: [32,128]@[128,6] + identity bias =====================
__global__ void k_fc2(const float* __restrict__ w2, const float* __restrict__ d2){
    int t = threadIdx.x; if(t>=192) return;
    int b = t/6, j = t - b*6;
    float s = d2[j];
    const float* x = g_x + b*128;
    #pragma unroll 8
    for(int i=0;i<128;i++) s += x[i]*w2[i*6+j];
    g_theta[t] = s;
}

// ================= grid sample: bilinear, zero padding =======================
__global__ void __launch_bounds__(256) k_sample(const float* __restrict__ in,
                                                float* __restrict__ out){
    int idx = blockIdx.x*256 + threadIdx.x;  // 32*256*256
    int x = idx & 255, y = (idx>>8)&255, b = idx>>16;
    const float* th = g_theta + b*6;
    float X = (2.f*x+1.f)*(1.f/256.f) - 1.f;
    float Y = (2.f*y+1.f)*(1.f/256.f) - 1.f;
    float gx = th[0]*X + th[1]*Y + th[2];
    float gy = th[3]*X + th[4]*Y + th[5];
    float px = (gx+1.f)*128.f - 0.5f;
    float py = (gy+1.f)*128.f - 0.5f;
    float x0f = floorf(px), y0f = floorf(py);
    int x0 = (int)x0f, y0 = (int)y0f;
    float wx1 = px - x0f, wx0 = 1.f - wx1;
    float wy1 = py - y0f, wy0 = 1.f - wy1;
    const float* ib = in + (size_t)b*256*256*3;
    float r0=0.f, r1=0.f, r2=0.f;
    #pragma unroll
    for(int dy=0;dy<2;dy++){
        int yy = y0+dy;
        if(yy<0 || yy>=256) continue;
        float wy = dy? wy1:wy0;
        #pragma unroll
        for(int dx=0;dx<2;dx++){
            int xx = x0+dx;
            if(xx<0 || xx>=256) continue;
            float w = wy * (dx? wx1:wx0);
            const float* p = ib + (yy*256+xx)*3;
            r0 += w*p[0]; r1 += w*p[1]; r2 += w*p[2];
        }
    }
    float* o = out + (size_t)idx*3;
    o[0]=r0; o[1]=r1; o[2]=r2;
}

// =============================================================================
extern "C" void kernel_launch(void* const* d_in, const int* in_sizes, int n_in,
                              void* d_out, int out_size){
    const float* in = (const float*)d_in[0];
    const float* k1 = (const float*)d_in[1];
    const float* b1 = (const float*)d_in[2];
    const float* k2 = (const float*)d_in[3];
    const float* b2 = (const float*)d_in[4];
    const float* w1 = (const float*)d_in[5];
    const float* d1 = (const float*)d_in[6];
    const float* w2 = (const float*)d_in[7];
    const float* d2 = (const float*)d_in[8];
    float* out = (float*)d_out;

    // idempotent, not stream-ordered: safe under capture, done every call
    cudaFuncSetAttribute(k_conv2, cudaFuncAttributeMaxDynamicSharedMemorySize, 106560);
    cudaFuncSetAttribute(k_fc1,   cudaFuncAttributeMaxDynamicSharedMemorySize, 69632);

    k_conv1 <<<2048, 256>>>(in, k1, b1);
    k_conv2 <<<dim3(4,4,32), 128, 106560>>>(k2, b2);
    k_fc1   <<<256, 128, 69632>>>(w1);
    k_fc1red<<<16, 256>>>(d1);
    k_fc2   <<<1, 192>>>(w2, d2);
    k_sample<<<8192, 256>>>(in, out);
}

// round 3
// speedup vs baseline: 1.0351x; 1.0351x over previous
#include <cuda_runtime.h>

// ---------------- f32x2 helpers (Blackwell packed fp32) ----------------------
static __device__ __forceinline__ unsigned long long pk2(float a, float b){
    unsigned long long r; asm("mov.b64 %0,{%1,%2};" : "=l"(r) : "f"(a), "f"(b)); return r;
}
static __device__ __forceinline__ float2 up2(unsigned long long v){
    float2 r; asm("mov.b64 {%0,%1},%2;" : "=f"(r.x), "=f"(r.y) : "l"(v)); return r;
}
static __device__ __forceinline__ void fma2(unsigned long long &d, unsigned long long a, unsigned long long b){
    asm("fma.rn.f32x2 %0,%1,%2,%0;" : "+l"(d) : "l"(a), "l"(b));
}
static __device__ __forceinline__ unsigned long long ld2(const float* p){
    return *reinterpret_cast<const unsigned long long*>(p);
}

// ---------------- scratch (device globals: no allocations allowed) -----------
__device__ float g_c1[32u*32*128*128];   // conv1 out PLANAR [B][32][128][128]
__device__ float g_c2[32u*64*64*64];     // conv2 out NHWC   [B][64][64][64]
__device__ float g_part[256*32*128];     // FC1 split-K partials
__device__ float g_part2[16*4096];       // FC1 reduction stage A out
__device__ float g_x[32*128];            // FC1 out (post relu)
__device__ float g_theta[32*6];          // FC2 out

// ================= conv1: 3x3 s2 SAME, 3->32, relu ===========================
// one thread per output pixel, 32 channels as 16 f32x2 accumulators.
// output planar [b][c][oy][ox] -> 32 coalesced STG.32 per thread.
__global__ void __launch_bounds__(256) k_conv1(const float* __restrict__ in,
                                               const float* __restrict__ k1,
                                               const float* __restrict__ b1){
    __shared__ float sw[864];   // [ky][kx][ci][32]
    __shared__ float sb[32];
    for(int i=threadIdx.x;i<864;i+=256) sw[i]=k1[i];
    if(threadIdx.x<32) sb[threadIdx.x]=b1[threadIdx.x];
    __syncthreads();

    int idx = blockIdx.x*256 + threadIdx.x;          // 32*128*128 = 524288
    int ox = idx & 127, oy = (idx>>7)&127, b = idx>>14;

    unsigned long long acc[16];
    #pragma unroll
    for(int j=0;j<16;j++) acc[j]=pk2(sb[2*j],sb[2*j+1]);

    const float* ib = in + (size_t)b*256*256*3;
    #pragma unroll
    for(int ky=0;ky<3;ky++){
        int iy = 2*oy+ky;                            // SAME: pad_lo = 0
        if(iy>=256) break;
        #pragma unroll
        for(int kx=0;kx<3;kx++){
            int ix = 2*ox+kx;
            if(ix>=256) continue;
            const float* p = ib + (iy*256+ix)*3;
            #pragma unroll
            for(int ci=0;ci<3;ci++){
                float v = p[ci];
                unsigned long long vv = pk2(v,v);
                const float* w = sw + ((ky*3+kx)*3+ci)*32;
                #pragma unroll
                for(int j=0;j<8;j++){
                    ulonglong2 wv = *reinterpret_cast<const ulonglong2*>(w+4*j);
                    fma2(acc[2*j],   vv, wv.x);
                    fma2(acc[2*j+1], vv, wv.y);
                }
            }
        }
    }
    float* o = g_c1 + (size_t)b*32*16384 + (oy*128+ox);
    #pragma unroll
    for(int j=0;j<16;j++){
        float2 v = up2(acc[j]);
        o[(2*j)*16384]   = v.x>0.f? v.x:0.f;
        o[(2*j+1)*16384] = v.y>0.f? v.y:0.f;
    }
}

// ================= conv2: 3x3 s2 SAME, 32->64, relu ==========================
// block: 16x16 output tile of one image. 256 threads: each thread = 4 pixels
// (rows oyq*4..+3, column oxl) x 16 output channels (quarter q).
// Two ci-group passes (16 ci each). smem = 104 KB, 2 blocks/SM, <=128 regs.
__global__ void __launch_bounds__(256,2) k_conv2(const float* __restrict__ k2,
                                                 const float* __restrict__ b2){
    extern __shared__ float sm[];
    float* sp  = sm;            // 16*1089 = 17424 floats (patch [ci][33*33])
    float* swt = sm + 17424;    // 9*16*64 = 9216 floats  (weights [tap][ci][64])

    int t = threadIdx.x;
    int q  = t>>6;              // channel quarter: ch q*16..q*16+15
    int pt = t&63;
    int oxl = pt&15, oyq = pt>>4;   // pixel col, row-quad

    int ox0 = blockIdx.x*16, oy0 = blockIdx.y*16, b = blockIdx.z;

    unsigned long long acc[4][8];
    #pragma unroll
    for(int j=0;j<8;j++){
        unsigned long long vv = pk2(b2[q*16+2*j], b2[q*16+2*j+1]);
        #pragma unroll
        for(int k=0;k<4;k++) acc[k][j]=vv;
    }

    const float* inb = g_c1 + (size_t)b*32*16384;   // planar [32][128][128]

    for(int g=0; g<2; g++){
        __syncthreads();
        // weights for this ci-group: swt[(tap*16+cil)*64 + co]
        for(int i=t;i<9216;i+=256){
            int co = i&63, rest = i>>6;            // rest = tap*16+cil
            swt[i] = k2[(((rest>>4)*32) + g*16 + (rest&15))*64 + co];
        }
        // input patch: 16 planes x 33x33, zero-fill OOB (pad hi only)
        #pragma unroll 1
        for(int ci=0;ci<16;ci++){
            const float* plane = inb + (size_t)(g*16+ci)*16384;
            for(int j=t;j<1089;j+=256){
                int ry = j/33, rx = j - ry*33;
                int iy = oy0*2+ry, ix = ox0*2+rx;
                float v = (iy<128 && ix<128)? plane[iy*128+ix] : 0.f;
                sp[ci*1089+j] = v;
            }
        }
        __syncthreads();

        #pragma unroll
        for(int ky=0;ky<3;ky++){
            #pragma unroll
            for(int kx=0;kx<3;kx++){
                #pragma unroll 4
                for(int ci=0;ci<16;ci++){
                    const float* w = swt + ((ky*3+kx)*16+ci)*64 + q*16;
                    ulonglong2 w01 = *reinterpret_cast<const ulonglong2*>(w);
                    ulonglong2 w23 = *reinterpret_cast<const ulonglong2*>(w+4);
                    ulonglong2 w45 = *reinterpret_cast<const ulonglong2*>(w+8);
                    ulonglong2 w67 = *reinterpret_cast<const ulonglong2*>(w+12);
                    const float* pc = sp + ci*1089 + (oyq*8+ky)*33 + kx + 2*oxl;
                    float v0 = pc[0], v1 = pc[66], v2 = pc[132], v3 = pc[198];
                    unsigned long long a0=pk2(v0,v0), a1=pk2(v1,v1),
                                       a2=pk2(v2,v2), a3=pk2(v3,v3);
                    #define C2STEP(K,A) \
                        fma2(acc[K][0], A, w01.x); fma2(acc[K][1], A, w01.y); \
                        fma2(acc[K][2], A, w23.x); fma2(acc[K][3], A, w23.y); \
                        fma2(acc[K][4], A, w45.x); fma2(acc[K][5], A, w45.y); \
                        fma2(acc[K][6], A, w67.x); fma2(acc[K][7], A, w67.y);
                    C2STEP(0,a0) C2STEP(1,a1) C2STEP(2,a2) C2STEP(3,a3)
                    #undef C2STEP
                }
            }
        }
    }
    #pragma unroll
    for(int k=0;k<4;k++){
        int oy = oy0 + oyq*4 + k, ox = ox0 + oxl;
        float* o = g_c2 + ((((size_t)b*64 + oy)*64 + ox)*64 + q*16);
        #pragma unroll
        for(int j=0;j<4;j++){
            float2 va = up2(acc[k][2*j]);
            float2 vb = up2(acc[k][2*j+1]);
            float4 v;
            v.x = va.x>0.f? va.x:0.f;  v.y = va.y>0.f? va.y:0.f;
            v.z = vb.x>0.f? vb.x:0.f;  v.w = vb.y>0.f? vb.y:0.f;
            *reinterpret_cast<float4*>(o + 4*j) = v;
        }
    }
}

// ================= FC1: [32,262144] @ [262144,128], split-K ==================
__global__ void __launch_bounds__(128) k_fc1(const float* __restrict__ w1){
    extern __shared__ float sa[];        // 512*34 floats
    int t = threadIdx.x;
    int nq = t & 31, mt = t >> 5;        // n = nq*4+j, m-pairs = mt*4+i
    int k0 = blockIdx.x * 1024;

    unsigned long long acc[4][4];
    #pragma unroll
    for(int i=0;i<4;i++)
        #pragma unroll
        for(int j=0;j<4;j++) acc[i][j]=0ull;

    for(int tile=0;tile<2;tile++){
        int kb = k0 + tile*512;
        __syncthreads();
        for(int i=t;i<16384;i+=128){
            int m = i>>9, kk = i&511;
            sa[kk*34+m] = g_c2[(size_t)m*262144 + kb + kk];
        }
        __syncthreads();
        #pragma unroll 8
        for(int kk=0;kk<512;kk++){
            float4 bv = *reinterpret_cast<const float4*>(
                w1 + (size_t)(kb+kk)*128 + nq*4);
            unsigned long long b0=pk2(bv.x,bv.x), b1=pk2(bv.y,bv.y),
                               b2=pk2(bv.z,bv.z), b3=pk2(bv.w,bv.w);
            const float* ap = sa + kk*34 + mt*8;
            #pragma unroll
            for(int i=0;i<4;i++){
                unsigned long long a2 = ld2(ap + 2*i);
                fma2(acc[i][0], a2, b0);
                fma2(acc[i][1], a2, b1);
                fma2(acc[i][2], a2, b2);
                fma2(acc[i][3], a2, b3);
            }
        }
    }
    float* pb = g_part + (size_t)blockIdx.x*4096;
    #pragma unroll
    for(int i=0;i<4;i++){
        int m0 = mt*8 + 2*i;
        #pragma unroll
        for(int j=0;j<4;j++){
            float2 v = up2(acc[i][j]);
            pb[m0*128     + nq*4 + j] = v.x;
            pb[(m0+1)*128 + nq*4 + j] = v.y;
        }
    }
}

// partial reduce stage A: 256 chunks -> 16, fully parallel, MLP=16
__global__ void k_redA(){
    int t = threadIdx.x;
    int og = blockIdx.x & 15, cg = blockIdx.x >> 4;
    int o = og*256 + t;
    float s = 0.f;
    #pragma unroll
    for(int c=0;c<16;c++) s += g_part[(size_t)(cg*16+c)*4096 + o];
    g_part2[cg*4096 + o] = s;
}

// stage B: 16 -> 1, + bias + relu
__global__ void k_redB(const float* __restrict__ d1){
    int o = blockIdx.x*256 + threadIdx.x;    // 4096
    float s = d1[o & 127];
    #pragma unroll
    for(int cg=0;cg<16;cg++) s += g_part2[cg*4096 + o];
    g_x[o] = s>0.f? s:0.f;
}

// ================= FC2: [32,128]@[128,6] + identity bias =====================
__global__ void k_fc2(const float* __restrict__ w2, const float* __restrict__ d2){
    int t = threadIdx.x; if(t>=192) return;
    int b = t/6, j = t - b*6;
    float s = d2[j];
    const float* x = g_x + b*128;
    #pragma unroll 8
    for(int i=0;i<128;i++) s += x[i]*w2[i*6+j];
    g_theta[t] = s;
}

// ================= grid sample: bilinear, zero padding =======================
__global__ void __launch_bounds__(256) k_sample(const float* __restrict__ in,
                                                float* __restrict__ out){
    int idx = blockIdx.x*256 + threadIdx.x;  // 32*256*256
    int x = idx & 255, y = (idx>>8)&255, b = idx>>16;
    const float* th = g_theta + b*6;
    float X = (2.f*x+1.f)*(1.f/256.f) - 1.f;
    float Y = (2.f*y+1.f)*(1.f/256.f) - 1.f;
    float gx = th[0]*X + th[1]*Y + th[2];
    float gy = th[3]*X + th[4]*Y + th[5];
    float px = (gx+1.f)*128.f - 0.5f;
    float py = (gy+1.f)*128.f - 0.5f;
    float x0f = floorf(px), y0f = floorf(py);
    int x0 = (int)x0f, y0 = (int)y0f;
    float wx1 = px - x0f, wx0 = 1.f - wx1;
    float wy1 = py - y0f, wy0 = 1.f - wy1;
    const float* ib = in + (size_t)b*256*256*3;
    float r0=0.f, r1=0.f, r2=0.f;
    #pragma unroll
    for(int dy=0;dy<2;dy++){
        int yy = y0+dy;
        if(yy<0 || yy>=256) continue;
        float wy = dy? wy1:wy0;
        #pragma unroll
        for(int dx=0;dx<2;dx++){
            int xx = x0+dx;
            if(xx<0 || xx>=256) continue;
            float w = wy * (dx? wx1:wx0);
            const float* p = ib + (yy*256+xx)*3;
            r0 += w*p[0]; r1 += w*p[1]; r2 += w*p[2];
        }
    }
    float* o = out + (size_t)idx*3;
    o[0]=r0; o[1]=r1; o[2]=r2;
}

// =============================================================================
extern "C" void kernel_launch(void* const* d_in, const int* in_sizes, int n_in,
                              void* d_out, int out_size){
    const float* in = (const float*)d_in[0];
    const float* k1 = (const float*)d_in[1];
    const float* b1 = (const float*)d_in[2];
    const float* k2 = (const float*)d_in[3];
    const float* b2 = (const float*)d_in[4];
    const float* w1 = (const float*)d_in[5];
    const float* d1 = (const float*)d_in[6];
    const float* w2 = (const float*)d_in[7];
    const float* d2 = (const float*)d_in[8];
    float* out = (float*)d_out;

    cudaFuncSetAttribute(k_conv2, cudaFuncAttributeMaxDynamicSharedMemorySize, 106560);
    cudaFuncSetAttribute(k_fc1,   cudaFuncAttributeMaxDynamicSharedMemorySize, 69632);

    k_conv1 <<<2048, 256>>>(in, k1, b1);
    k_conv2 <<<dim3(4,4,32), 256, 106560>>>(k2, b2);
    k_fc1   <<<256, 128, 69632>>>(w1);
    k_redA  <<<256, 256>>>();
    k_redB  <<<16, 256>>>(d1);
    k_fc2   <<<1, 192>>>(w2, d2);
    k_sample<<<8192, 256>>>(in, out);
}